// round 12
// baseline (speedup 1.0000x reference)
#include <cuda_runtime.h>
#include <cstdint>

// ---------------- problem constants ----------------
#define K_DIM       2048
#define N_DIM       1024
#define ROWS_WHOLE  8192
#define ROWS_PARTS  32768
#define ROWS_TOTAL  40960
#define MB_WHOLE    64
#define MB_TOTAL    320

// ---------------- tile config ----------------
#define BM 128
#define BN 64
#define BK 32                       // k per chunk (one m16n8k32 IMMA step)
#define NCHUNK (K_DIM / BK)         // 64
#define RS 48                       // smem row stride in bytes (conflict-free)

// stage byte offsets
#define A0_B   0
#define A1_B   6144
#define A2_B   12288
#define B0_B   18432
#define B1_B   21504
#define STAGE_B 24576
#define BIAS_B  (2 * STAGE_B)       // 49152
#define SMEM_BYTES (BIAS_B + BN * 4)  // 49408

__device__ float g_sumsq[ROWS_TOTAL];

// ---------------- helpers ----------------
__device__ __forceinline__ void imma32(int* c,
                                       uint32_t a0, uint32_t a1, uint32_t a2, uint32_t a3,
                                       uint32_t b0, uint32_t b1) {
    asm volatile(
        "mma.sync.aligned.m16n8k32.row.col.s32.s8.s8.s32 "
        "{%0,%1,%2,%3}, {%4,%5,%6,%7}, {%8,%9}, {%0,%1,%2,%3};"
        : "+r"(c[0]), "+r"(c[1]), "+r"(c[2]), "+r"(c[3])
        : "r"(a0), "r"(a1), "r"(a2), "r"(a3), "r"(b0), "r"(b1));
}

__device__ __forceinline__ uint32_t pack4(int v0, int v1, int v2, int v3) {
    uint32_t t, d;
    uint32_t zero = 0;
    asm("cvt.pack.sat.s8.s32.b32 %0, %1, %2, %3;" : "=r"(t) : "r"(v3), "r"(v2), "r"(zero));
    asm("cvt.pack.sat.s8.s32.b32 %0, %1, %2, %3;" : "=r"(d) : "r"(v1), "r"(v0), "r"(t));
    return d;   // bytes [v0,v1,v2,v3] little-endian
}

// A split: a = i0*2^-4 + i1*2^-12 + i2*2^-19 (+ err <= 2^-19)
__device__ __forceinline__ void cvtA(float v, int& i0, int& i1, int& i2) {
    i0 = __float2int_rn(v * 16.0f);
    float r1 = fmaf((float)i0, -0x1p-4f, v);     // exact, |r1| <= 2^-5
    i1 = (int)(r1 * 4096.0f);                    // trunc -> |i1| <= 127
    float r2 = fmaf((float)i1, -0x1p-12f, r1);   // exact, |r2| < 2^-12
    i2 = (int)(r2 * 0x1p19f);                    // trunc -> |i2| <= 127
}
// B split: b = j0*2^-11 + j1*2^-19 (+ err <= 2^-20; sat-pack handles the +/-128 tie)
__device__ __forceinline__ void cvtB(float v, int& j0, int& j1) {
    j0 = __float2int_rn(v * 2048.0f);
    float r1 = fmaf((float)j0, -0x1p-11f, v);    // exact, |r1| <= 2^-12
    j1 = __float2int_rn(r1 * 0x1p19f);
}

__global__ void zero_kernel() {
    int i = blockIdx.x * 256 + threadIdx.x;
    if (i < ROWS_TOTAL) g_sumsq[i] = 0.0f;
}

// ---------------- merged int8 4-term split GEMM + row sum-of-squares ----------------
__global__ __launch_bounds__(256)
void gemm_s8_kernel(const float* __restrict__ Acur,
                    const float* __restrict__ Ahist,
                    const float* __restrict__ Ww,
                    const float* __restrict__ bw,
                    const float* __restrict__ Wp,
                    const float* __restrict__ bp)
{
    extern __shared__ __align__(16) char smem[];
    const int tid = threadIdx.x;
    const int wid = tid >> 5;
    const int lid = tid & 31;
    const int wm  = wid >> 1;          // 0..3 : warp row (32 rows)
    const int wn  = wid & 1;           // 0..1 : warp col (32 cols)
    const int r   = lid >> 2;          // 0..7
    const int cq  = lid & 3;           // 0..3
    const int by  = blockIdx.y;
    const int n0  = blockIdx.x * BN;

    const bool is_whole = (by < MB_WHOLE);
    const float* A    = is_whole ? Acur : Ahist;
    const float* W    = is_whole ? Ww   : Wp;
    const float* bias = is_whole ? bw   : bp;
    const int m0      = (is_whole ? by : (by - MB_WHOLE)) * BM;
    const int row_off = is_whole ? 0 : ROWS_WHOLE;

    float* sbias = (float*)(smem + BIAS_B);
    if (tid < BN) sbias[tid] = bias[n0 + tid];

    // loader coords
    const int arow  = tid >> 1;            // 0..127
    const int khalf = (tid & 1) << 4;      // 0 or 16
    const int brow  = tid >> 2;            // 0..63
    const int bk    = (tid & 3) << 3;      // 0,8,16,24
    const float4* Ap = (const float4*)(A + (size_t)(m0 + arow) * K_DIM + khalf);
    const float4* Bp = (const float4*)(W + (size_t)(n0 + brow) * K_DIM + bk);

    int S1[2][4][4], S2[2][4][4], S3[2][4][4];
#pragma unroll
    for (int i = 0; i < 2; i++)
#pragma unroll
        for (int j = 0; j < 4; j++)
#pragma unroll
            for (int q = 0; q < 4; q++) { S1[i][j][q] = 0; S2[i][j][q] = 0; S3[i][j][q] = 0; }

    float4 av[4], bv[2];

#define LOADCHUNK(kc) do { \
        av[0] = Ap[(kc) * 8 + 0]; av[1] = Ap[(kc) * 8 + 1]; \
        av[2] = Ap[(kc) * 8 + 2]; av[3] = Ap[(kc) * 8 + 3]; \
        bv[0] = Bp[(kc) * 8 + 0]; bv[1] = Bp[(kc) * 8 + 1]; \
    } while (0)

#define STORESTAGE(s) do { \
        char* st_ = smem + (s) * STAGE_B; \
        uint32_t w0[4], w1[4], w2[4]; \
        _Pragma("unroll") \
        for (int g = 0; g < 4; g++) { \
            int x0,x1,x2, y0,y1,y2, z0,z1,z2, u0,u1,u2; \
            cvtA(av[g].x, x0, x1, x2); \
            cvtA(av[g].y, y0, y1, y2); \
            cvtA(av[g].z, z0, z1, z2); \
            cvtA(av[g].w, u0, u1, u2); \
            w0[g] = pack4(x0, y0, z0, u0); \
            w1[g] = pack4(x1, y1, z1, u1); \
            w2[g] = pack4(x2, y2, z2, u2); \
        } \
        const int aoff = arow * RS + khalf; \
        *(uint4*)(st_ + A0_B + aoff) = make_uint4(w0[0], w0[1], w0[2], w0[3]); \
        *(uint4*)(st_ + A1_B + aoff) = make_uint4(w1[0], w1[1], w1[2], w1[3]); \
        *(uint4*)(st_ + A2_B + aoff) = make_uint4(w2[0], w2[1], w2[2], w2[3]); \
        uint32_t p0[2], p1[2]; \
        _Pragma("unroll") \
        for (int g = 0; g < 2; g++) { \
            int x0,x1, y0,y1, z0,z1, u0,u1; \
            cvtB(bv[g].x, x0, x1); \
            cvtB(bv[g].y, y0, y1); \
            cvtB(bv[g].z, z0, z1); \
            cvtB(bv[g].w, u0, u1); \
            p0[g] = pack4(x0, y0, z0, u0); \
            p1[g] = pack4(x1, y1, z1, u1); \
        } \
        const int boff = brow * RS + bk; \
        *(uint2*)(st_ + B0_B + boff) = make_uint2(p0[0], p0[1]); \
        *(uint2*)(st_ + B1_B + boff) = make_uint2(p1[0], p1[1]); \
    } while (0)

    LOADCHUNK(0);
    STORESTAGE(0);
    LOADCHUNK(1);
    __syncthreads();

    for (int kc = 0; kc < NCHUNK; kc++) {
        const char* st = smem + (kc & 1) * STAGE_B;

        // B fragments: 2 terms x 4 nf x 2 regs
        uint32_t fb0[4][2], fb1[4][2];
#pragma unroll
        for (int nf = 0; nf < 4; nf++) {
            const int coff = (wn * 32 + nf * 8 + r) * RS + 4 * cq;
            fb0[nf][0] = *(const uint32_t*)(st + B0_B + coff);
            fb0[nf][1] = *(const uint32_t*)(st + B0_B + coff + 16);
            fb1[nf][0] = *(const uint32_t*)(st + B1_B + coff);
            fb1[nf][1] = *(const uint32_t*)(st + B1_B + coff + 16);
        }

#pragma unroll
        for (int mf = 0; mf < 2; mf++) {
            const int ro0 = (wm * 32 + mf * 16 + r) * RS + 4 * cq;
            const int ro1 = ro0 + 8 * RS;
            uint32_t a00 = *(const uint32_t*)(st + A0_B + ro0);
            uint32_t a01 = *(const uint32_t*)(st + A0_B + ro1);
            uint32_t a02 = *(const uint32_t*)(st + A0_B + ro0 + 16);
            uint32_t a03 = *(const uint32_t*)(st + A0_B + ro1 + 16);
            uint32_t a10 = *(const uint32_t*)(st + A1_B + ro0);
            uint32_t a11 = *(const uint32_t*)(st + A1_B + ro1);
            uint32_t a12 = *(const uint32_t*)(st + A1_B + ro0 + 16);
            uint32_t a13 = *(const uint32_t*)(st + A1_B + ro1 + 16);
            uint32_t a20 = *(const uint32_t*)(st + A2_B + ro0);
            uint32_t a21 = *(const uint32_t*)(st + A2_B + ro1);
            uint32_t a22 = *(const uint32_t*)(st + A2_B + ro0 + 16);
            uint32_t a23 = *(const uint32_t*)(st + A2_B + ro1 + 16);
#pragma unroll
            for (int nf = 0; nf < 4; nf++) {
                imma32(S1[mf][nf], a00, a01, a02, a03, fb0[nf][0], fb0[nf][1]); // a0*b0  2^-15
                imma32(S2[mf][nf], a00, a01, a02, a03, fb1[nf][0], fb1[nf][1]); // a0*b1  2^-23
                imma32(S2[mf][nf], a10, a11, a12, a13, fb0[nf][0], fb0[nf][1]); // a1*b0  2^-23
                imma32(S3[mf][nf], a20, a21, a22, a23, fb0[nf][0], fb0[nf][1]); // a2*b0  2^-30
            }
        }

        if (kc + 1 < NCHUNK) {
            STORESTAGE((kc + 1) & 1);
            if (kc + 2 < NCHUNK) LOADCHUNK(kc + 2);
        }
        __syncthreads();
    }

    // ---------------- epilogue: compose, bias, square, per-row reduce, atomic ----------------
#pragma unroll
    for (int mf = 0; mf < 2; mf++) {
        float rs0 = 0.f, rs1 = 0.f;
#pragma unroll
        for (int nf = 0; nf < 4; nf++) {
            const int nc = wn * 32 + nf * 8 + 2 * cq;
            float b0 = sbias[nc], b1 = sbias[nc + 1];
#pragma unroll
            for (int q = 0; q < 4; q++) {
                float c = fmaf((float)S2[mf][nf][q], 0x1p-23f,
                               (float)S1[mf][nf][q] * 0x1p-15f);
                c = fmaf((float)S3[mf][nf][q], 0x1p-30f, c);
                c += (q & 1) ? b1 : b0;
                if (q < 2) rs0 += c * c; else rs1 += c * c;
            }
        }
        rs0 += __shfl_xor_sync(0xffffffffu, rs0, 1);
        rs0 += __shfl_xor_sync(0xffffffffu, rs0, 2);
        rs1 += __shfl_xor_sync(0xffffffffu, rs1, 1);
        rs1 += __shfl_xor_sync(0xffffffffu, rs1, 2);
        if (cq == 0) {
            const int mrow = row_off + m0 + wm * 32 + mf * 16 + r;
            atomicAdd(&g_sumsq[mrow],     rs0);
            atomicAdd(&g_sumsq[mrow + 8], rs1);
        }
    }
}

// ---------------- finalize ----------------
__global__ void finalize_kernel(const float* __restrict__ phi_scale,
                                const float* __restrict__ phi_bias,
                                float* __restrict__ out)
{
    const int b = blockIdx.x;
    const int tid = threadIdx.x;

    float lw = 0.f, lp = 0.f;
    for (int i = tid; i < 2048; i += 256)
        lw += sqrtf(g_sumsq[b * 2048 + i]);
#pragma unroll
    for (int h = 0; h < 4; h++) {
        int base = ROWS_WHOLE + h * ROWS_WHOLE + b * 2048;
        for (int i = tid; i < 2048; i += 256)
            lp += sqrtf(g_sumsq[base + i]);
    }

    __shared__ float sw[256];
    __shared__ float sp[256];
    sw[tid] = lw; sp[tid] = lp;
    __syncthreads();
    for (int s = 128; s > 0; s >>= 1) {
        if (tid < s) { sw[tid] += sw[tid + s]; sp[tid] += sp[tid + s]; }
        __syncthreads();
    }
    if (tid == 0) {
        float w = sw[0] / 2048.0f;
        float p = sp[0] / 8192.0f;
        float raw = (w - p) / (w + 1e-8f);
        float phi = phi_scale[0] * raw + phi_bias[0];
        out[b] = fminf(fmaxf(phi, 0.0f), 1.0f);
    }
}

extern "C" void kernel_launch(void* const* d_in, const int* in_sizes, int n_in,
                              void* d_out, int out_size)
{
    const float* cur  = (const float*)d_in[0];   // [4,2048,2048]
    const float* hist = (const float*)d_in[1];   // [4,4,2048,2048]
    const float* Ww   = (const float*)d_in[2];   // [1024,2048]
    const float* bw   = (const float*)d_in[3];   // [1024]
    const float* Wp   = (const float*)d_in[4];   // [1024,2048]
    const float* bp   = (const float*)d_in[5];   // [1024]
    const float* ps   = (const float*)d_in[6];
    const float* pb   = (const float*)d_in[7];
    float* out = (float*)d_out;                  // [4]

    cudaFuncSetAttribute(gemm_s8_kernel,
                         cudaFuncAttributeMaxDynamicSharedMemorySize, SMEM_BYTES);

    zero_kernel<<<(ROWS_TOTAL + 255) / 256, 256>>>();

    gemm_s8_kernel<<<dim3(N_DIM / BN, MB_TOTAL), 256, SMEM_BYTES>>>(
        cur, hist, Ww, bw, Wp, bp);

    finalize_kernel<<<4, 256>>>(ps, pb, out);
}

// round 13
// speedup vs baseline: 1.4403x; 1.4403x over previous
#include <cuda_runtime.h>
#include <cuda_fp16.h>
#include <cstdint>

// ---------------- problem constants ----------------
#define K_DIM       2048
#define N_DIM       1024
#define ROWS_WHOLE  8192
#define ROWS_PARTS  32768
#define ROWS_TOTAL  40960
#define MB_WHOLE    64
#define NTILES      2560           // 8 x 320 tiles
#define GRID_P      296            // persistent CTAs = 148 SMs x 2

// ---------------- tile config (R6/R11 architecture) ----------------
#define BM 128
#define BN 128
#define BK 16
#define NCHUNK (K_DIM / BK)        // 128
#define SH 24                      // halves per smem row (48B stride, conflict-free)

#define TERM_H   (BM * SH)
#define AH0_B    0
#define AH1_B    (TERM_H * 2)
#define BH0_B    (2 * TERM_H * 2)
#define BH1_B    (3 * TERM_H * 2)
#define STAGE_B  (4 * TERM_H * 2)      // 24576 bytes per stage
#define BIAS_B   (2 * STAGE_B)
#define TILE_B   (BIAS_B + BN * 4)     // tile-ticket broadcast slot
#define SMEM_BYTES (TILE_B + 16)

__device__ float g_sumsq[ROWS_TOTAL];
__device__ unsigned int g_tile;

// ---------------- helpers ----------------
__device__ __forceinline__ void mma16(float* c,
                                      uint32_t a0, uint32_t a1, uint32_t a2, uint32_t a3,
                                      uint32_t b0, uint32_t b1) {
    asm volatile(
        "mma.sync.aligned.m16n8k16.row.col.f32.f16.f16.f32 "
        "{%0,%1,%2,%3}, {%4,%5,%6,%7}, {%8,%9}, {%0,%1,%2,%3};"
        : "+f"(c[0]), "+f"(c[1]), "+f"(c[2]), "+f"(c[3])
        : "r"(a0), "r"(a1), "r"(a2), "r"(a3), "r"(b0), "r"(b1));
}

__device__ __forceinline__ void split8(float4 v0, float4 v1, uint4& H0, uint4& H1) {
    __half2 p0 = __floats2half2_rn(v0.x, v0.y);
    __half2 p1 = __floats2half2_rn(v0.z, v0.w);
    __half2 p2 = __floats2half2_rn(v1.x, v1.y);
    __half2 p3 = __floats2half2_rn(v1.z, v1.w);
    float2 q0 = __half22float2(p0);
    float2 q1 = __half22float2(p1);
    float2 q2 = __half22float2(p2);
    float2 q3 = __half22float2(p3);
    __half2 r0 = __floats2half2_rn(v0.x - q0.x, v0.y - q0.y);
    __half2 r1 = __floats2half2_rn(v0.z - q1.x, v0.w - q1.y);
    __half2 r2 = __floats2half2_rn(v1.x - q2.x, v1.y - q2.y);
    __half2 r3 = __floats2half2_rn(v1.z - q3.x, v1.w - q3.y);
    H0 = make_uint4(*(uint32_t*)&p0, *(uint32_t*)&p1, *(uint32_t*)&p2, *(uint32_t*)&p3);
    H1 = make_uint4(*(uint32_t*)&r0, *(uint32_t*)&r1, *(uint32_t*)&r2, *(uint32_t*)&r3);
}

__global__ void zero_kernel() {
    int i = blockIdx.x * 256 + threadIdx.x;
    if (i < ROWS_TOTAL) g_sumsq[i] = 0.0f;
    if (i == 0) g_tile = 0u;
}

// ---------------- persistent fp16x2-split GEMM + row sum-of-squares ----------------
__global__ __launch_bounds__(256, 2)
void gemm_fp16x2_kernel(const float* __restrict__ Acur,
                        const float* __restrict__ Ahist,
                        const float* __restrict__ Ww,
                        const float* __restrict__ bw,
                        const float* __restrict__ Wp,
                        const float* __restrict__ bp)
{
    extern __shared__ __align__(16) char smem[];
    const int tid = threadIdx.x;
    const int wid = tid >> 5;
    const int lid = tid & 31;
    const int wm  = wid >> 2;
    const int wn  = wid & 3;
    const int r   = lid >> 2;
    const int cq  = lid & 3;

    float* sbias = (float*)(smem + BIAS_B);
    unsigned int* stile = (unsigned int*)(smem + TILE_B);

    const int ar = tid >> 1;
    const int ac = (tid & 1) << 3;
    const uint32_t s_off = (uint32_t)ar * (SH * 2) + (uint32_t)ac * 2;

    for (;;) {
        // grab next tile (the sync also fences the previous tile's epilogue
        // reads of smem against this tile's smem writes)
        if (tid == 0) *stile = atomicAdd(&g_tile, 1u);
        __syncthreads();
        const unsigned int t = *stile;
        if (t >= NTILES) break;

        const int bx = (int)(t & 7u);          // 0..7   (N tiles, fastest)
        const int by = (int)(t >> 3);          // 0..319 (M tiles)
        const int n0 = bx * BN;

        const bool is_whole = (by < MB_WHOLE);
        const float* A    = is_whole ? Acur : Ahist;
        const float* W    = is_whole ? Ww   : Wp;
        const float* bias = is_whole ? bw   : bp;
        const int m0      = (is_whole ? by : (by - MB_WHOLE)) * BM;
        const int row_off = is_whole ? 0 : ROWS_WHOLE;

        if (tid < BN) sbias[tid] = bias[n0 + tid];

        const float* Aptr = A + (size_t)(m0 + ar) * K_DIM + ac;
        const float* Wptr = W + (size_t)(n0 + ar) * K_DIM + ac;

        float acc[4][4][4];
#pragma unroll
        for (int i = 0; i < 4; i++)
#pragma unroll
            for (int j = 0; j < 4; j++)
#pragma unroll
                for (int q = 0; q < 4; q++) acc[i][j][q] = 0.f;

        float4 av0, av1, bv0, bv1;

#define LOADCHUNK(kc) do { \
        const float* ap_ = Aptr + (size_t)(kc) * BK; \
        av0 = *(const float4*)ap_;  av1 = *(const float4*)(ap_ + 4); \
        const float* wp_ = Wptr + (size_t)(kc) * BK; \
        bv0 = *(const float4*)wp_;  bv1 = *(const float4*)(wp_ + 4); \
    } while (0)

#define STORESTAGE(s) do { \
        char* st_ = smem + (s) * STAGE_B; \
        uint4 H0_, H1_; \
        split8(av0, av1, H0_, H1_); \
        *(uint4*)(st_ + AH0_B + s_off) = H0_; \
        *(uint4*)(st_ + AH1_B + s_off) = H1_; \
        split8(bv0, bv1, H0_, H1_); \
        *(uint4*)(st_ + BH0_B + s_off) = H0_; \
        *(uint4*)(st_ + BH1_B + s_off) = H1_; \
    } while (0)

        LOADCHUNK(0);
        STORESTAGE(0);
        LOADCHUNK(1);
        __syncthreads();

        for (int kc = 0; kc < NCHUNK; kc++) {
            const char* st = smem + (kc & 1) * STAGE_B;

            uint32_t b0h[4], b1h[4], b0l[4], b1l[4];
#pragma unroll
            for (int nf = 0; nf < 4; nf++) {
                const int off = ((wn * 32 + nf * 8 + r) * SH + 2 * cq) * 2;
                b0h[nf] = *(const uint32_t*)(st + BH0_B + off);
                b1h[nf] = *(const uint32_t*)(st + BH0_B + off + 16);
                b0l[nf] = *(const uint32_t*)(st + BH1_B + off);
                b1l[nf] = *(const uint32_t*)(st + BH1_B + off + 16);
            }

#pragma unroll
            for (int mf = 0; mf < 4; mf++) {
                const int off0 = ((wm * 64 + mf * 16 + r) * SH + 2 * cq) * 2;
                const int off1 = off0 + 8 * SH * 2;
                uint32_t ah0 = *(const uint32_t*)(st + AH0_B + off0);
                uint32_t ah1 = *(const uint32_t*)(st + AH0_B + off1);
                uint32_t ah2 = *(const uint32_t*)(st + AH0_B + off0 + 16);
                uint32_t ah3 = *(const uint32_t*)(st + AH0_B + off1 + 16);
                uint32_t al0 = *(const uint32_t*)(st + AH1_B + off0);
                uint32_t al1 = *(const uint32_t*)(st + AH1_B + off1);
                uint32_t al2 = *(const uint32_t*)(st + AH1_B + off0 + 16);
                uint32_t al3 = *(const uint32_t*)(st + AH1_B + off1 + 16);
#pragma unroll
                for (int nf = 0; nf < 4; nf++) {
                    mma16(acc[mf][nf], ah0, ah1, ah2, ah3, b0h[nf], b1h[nf]);  // h0*h0
                    mma16(acc[mf][nf], ah0, ah1, ah2, ah3, b0l[nf], b1l[nf]);  // h0*h1
                    mma16(acc[mf][nf], al0, al1, al2, al3, b0h[nf], b1h[nf]);  // h1*h0
                }
            }

            if (kc + 1 < NCHUNK) {
                STORESTAGE((kc + 1) & 1);
                if (kc + 2 < NCHUNK) LOADCHUNK(kc + 2);
            }
            __syncthreads();
        }

        // ---------------- epilogue: bias, square, per-row reduce, atomic ----------------
#pragma unroll
        for (int mf = 0; mf < 4; mf++) {
            float rs0 = 0.f, rs1 = 0.f;
#pragma unroll
            for (int nf = 0; nf < 4; nf++) {
                const int nc = wn * 32 + nf * 8 + 2 * cq;
                float b0 = sbias[nc], b1 = sbias[nc + 1];
                float v;
                v = acc[mf][nf][0] + b0; rs0 += v * v;
                v = acc[mf][nf][1] + b1; rs0 += v * v;
                v = acc[mf][nf][2] + b0; rs1 += v * v;
                v = acc[mf][nf][3] + b1; rs1 += v * v;
            }
            rs0 += __shfl_xor_sync(0xffffffffu, rs0, 1);
            rs0 += __shfl_xor_sync(0xffffffffu, rs0, 2);
            rs1 += __shfl_xor_sync(0xffffffffu, rs1, 1);
            rs1 += __shfl_xor_sync(0xffffffffu, rs1, 2);
            if (cq == 0) {
                const int mrow = row_off + m0 + wm * 64 + mf * 16 + r;
                atomicAdd(&g_sumsq[mrow],     rs0);
                atomicAdd(&g_sumsq[mrow + 8], rs1);
            }
        }
    }
}

// ---------------- finalize ----------------
__global__ void finalize_kernel(const float* __restrict__ phi_scale,
                                const float* __restrict__ phi_bias,
                                float* __restrict__ out)
{
    const int b = blockIdx.x;
    const int tid = threadIdx.x;

    float lw = 0.f, lp = 0.f;
    for (int i = tid; i < 2048; i += 256)
        lw += sqrtf(g_sumsq[b * 2048 + i]);
#pragma unroll
    for (int h = 0; h < 4; h++) {
        int base = ROWS_WHOLE + h * ROWS_WHOLE + b * 2048;
        for (int i = tid; i < 2048; i += 256)
            lp += sqrtf(g_sumsq[base + i]);
    }

    __shared__ float sw[256];
    __shared__ float sp[256];
    sw[tid] = lw; sp[tid] = lp;
    __syncthreads();
    for (int s = 128; s > 0; s >>= 1) {
        if (tid < s) { sw[tid] += sw[tid + s]; sp[tid] += sp[tid + s]; }
        __syncthreads();
    }
    if (tid == 0) {
        float w = sw[0] / 2048.0f;
        float p = sp[0] / 8192.0f;
        float raw = (w - p) / (w + 1e-8f);
        float phi = phi_scale[0] * raw + phi_bias[0];
        out[b] = fminf(fmaxf(phi, 0.0f), 1.0f);
    }
}

extern "C" void kernel_launch(void* const* d_in, const int* in_sizes, int n_in,
                              void* d_out, int out_size)
{
    const float* cur  = (const float*)d_in[0];   // [4,2048,2048]
    const float* hist = (const float*)d_in[1];   // [4,4,2048,2048]
    const float* Ww   = (const float*)d_in[2];   // [1024,2048]
    const float* bw   = (const float*)d_in[3];   // [1024]
    const float* Wp   = (const float*)d_in[4];   // [1024,2048]
    const float* bp   = (const float*)d_in[5];   // [1024]
    const float* ps   = (const float*)d_in[6];
    const float* pb   = (const float*)d_in[7];
    float* out = (float*)d_out;                  // [4]

    cudaFuncSetAttribute(gemm_fp16x2_kernel,
                         cudaFuncAttributeMaxDynamicSharedMemorySize, SMEM_BYTES);

    zero_kernel<<<(ROWS_TOTAL + 255) / 256, 256>>>();

    gemm_fp16x2_kernel<<<GRID_P, 256, SMEM_BYTES>>>(cur, hist, Ww, bw, Wp, bp);

    finalize_kernel<<<4, 256>>>(ps, pb, out);
}